// round 10
// baseline (speedup 1.0000x reference)
#include <cuda_runtime.h>
#include <cuda_fp16.h>
#include <cstdint>

#define TOK   16384
#define DIN   256
#define DH    2048
#define NQKV  (3 * DH)   // 6144
#define HEADS 8

// ---------------- device scratch ----------------
__device__ __half g_Xh[(size_t)TOK * DIN];
__device__ __half g_QKV[(size_t)TOK * NQKV];    // [t][Q 0..2047 | K 2048.. | V 4096..]
__device__ __half g_Oh[(size_t)TOK * DH];
__device__ __half g_Wqkv[NQKV * DIN];           // [n][k] rows: Wq, Wk, Wv
__device__ __half g_Wo[DIN * DH];               // Wo^T [n=256][k=2048]
__device__ float  g_bqkv[NQKV];

// ---------------- helpers ----------------
__device__ __forceinline__ uint32_t smem_u32(const void* p) {
    uint32_t a;
    asm("{ .reg .u64 t; cvta.to.shared.u64 t, %1; cvt.u32.u64 %0, t; }" : "=r"(a) : "l"(p));
    return a;
}
__device__ __forceinline__ void cpa16(uint32_t dst, const void* src) {
    asm volatile("cp.async.cg.shared.global [%0], [%1], 16;" :: "r"(dst), "l"(src));
}
#define CP_COMMIT() asm volatile("cp.async.commit_group;" ::: "memory")
#define CP_WAIT(n)  asm volatile("cp.async.wait_group %0;" :: "n"(n) : "memory")

#define LDSM4(r, a) asm volatile( \
    "ldmatrix.sync.aligned.m8n8.x4.shared.b16 {%0,%1,%2,%3}, [%4];" \
    : "=r"((r)[0]), "=r"((r)[1]), "=r"((r)[2]), "=r"((r)[3]) : "r"(a))

#define MMA16816(c, a, b0, b1) asm volatile( \
    "mma.sync.aligned.m16n8k16.row.col.f32.f16.f16.f32 " \
    "{%0,%1,%2,%3}, {%4,%5,%6,%7}, {%8,%9}, {%0,%1,%2,%3};" \
    : "+f"((c)[0]), "+f"((c)[1]), "+f"((c)[2]), "+f"((c)[3]) \
    : "r"((a)[0]), "r"((a)[1]), "r"((a)[2]), "r"((a)[3]), "r"(b0), "r"(b1))

// ============================================================================
// X convert: fp32 -> fp16
// ============================================================================
__global__ void xconv(const float4* __restrict__ x) {
    size_t i = (size_t)blockIdx.x * blockDim.x + threadIdx.x;
    float4 f = x[i];
    __half2* p = reinterpret_cast<__half2*>(g_Xh) + 2 * i;
    p[0] = __floats2half2_rn(f.x, f.y);
    p[1] = __floats2half2_rn(f.z, f.w);
}

// ============================================================================
// weight transpose: W[K][N] -> [N][K] fp16 (QKV into one array) + bias concat
// ============================================================================
__global__ void wconv_all(const float* __restrict__ Wq, const float* __restrict__ Wk,
                          const float* __restrict__ Wv, const float* __restrict__ Wo,
                          const float* __restrict__ bq, const float* __restrict__ bk,
                          const float* __restrict__ bv) {
    __shared__ float s[64][65];
    const int which = blockIdx.y;
    const float* W; __half* oh; int K, N;
    if (which == 0)      { W = Wq; oh = g_Wqkv;              K = DIN; N = DH; }
    else if (which == 1) { W = Wk; oh = g_Wqkv + DH * DIN;   K = DIN; N = DH; }
    else if (which == 2) { W = Wv; oh = g_Wqkv + 2 * DH * DIN; K = DIN; N = DH; }
    else                 { W = Wo; oh = g_Wo;                K = DH;  N = DIN; }
    const int nt = N / 64;
    const int n0 = (blockIdx.x % nt) * 64, k0 = (blockIdx.x / nt) * 64;
    const int tx = threadIdx.x & 63, ty = threadIdx.x >> 6;
    for (int r = ty; r < 64; r += 4)
        s[r][tx] = W[(size_t)(k0 + r) * N + n0 + tx];
    __syncthreads();
    for (int r = ty; r < 64; r += 4)
        oh[(size_t)(n0 + r) * K + k0 + tx] = __float2half_rn(s[tx][r]);
    // bias concat (block (0, y<3) only, once per weight)
    if (which < 3 && blockIdx.x == 0) {
        const float* b = (which == 0) ? bq : (which == 1) ? bk : bv;
        for (int i = threadIdx.x; i < DH; i += 256)
            g_bqkv[which * DH + i] = b[i];
    }
}

// ============================================================================
// bias prefill for split-K output: out[t][c] = bo[c]   (4096 blocks x 256)
// ============================================================================
__global__ void biasfill(float* __restrict__ out, const float* __restrict__ bo) {
    __shared__ float4 sb[64];
    if (threadIdx.x < 64) sb[threadIdx.x] = ((const float4*)bo)[threadIdx.x];
    __syncthreads();
    size_t i = (size_t)blockIdx.x * blockDim.x + threadIdx.x;
    ((float4*)out)[i] = sb[i & 63];
}

// ============================================================================
// fp16 TN GEMM: C[M][ldc] = A[M][*] @ B[N][*]^T (+bias)
// CTA 128x128, 8 warps (2m x 4n), warp tile 64x32, BK=64 (64 MMA per sync).
// 3-stage cp.async pipeline; stage = A(18432)+B(18432) = 36864B, pitch 144B.
// 3 stages = 110592B -> 2 CTA/SM (216KB of 228KB).
// MODE 0: half out + bias.  MODE 2: float atomicAdd (bias prefilled).
// ============================================================================
#define BK    64
#define GST   36864
#define GSMEM (3 * GST)

template <int MODE>
__global__ void __launch_bounds__(256, 2)
hgemm(const __half* __restrict__ A, int lda,
      const __half* __restrict__ B, int ldb,
      const float* __restrict__ bias, void* __restrict__ Cv, int ldc, int K)
{
    extern __shared__ char smem[];
    const uint32_t sbase = smem_u32(smem);
    const int tid = threadIdx.x, lane = tid & 31, wid = tid >> 5;
    const int wm = wid >> 2, wn = wid & 3;
    const size_t m0 = (size_t)blockIdx.x * 128;
    const size_t n0 = (size_t)blockIdx.y * 128;
    const size_t k0 = (size_t)blockIdx.z * K;     // split-K offset

    float acc[4][4][4];
    #pragma unroll
    for (int a = 0; a < 4; a++)
        #pragma unroll
        for (int b = 0; b < 4; b++)
            #pragma unroll
            for (int c = 0; c < 4; c++) acc[a][b][c] = 0.f;

    const int r = tid >> 1;                 // 0..127
    const int half64 = (tid & 1);           // which 64B half of the 128B row
    const int KT = K / BK;

    #define LOAD_STAGE(s, kb) do { \
        uint32_t d = sbase + (s) * GST + r * 144 + half64 * 64; \
        const __half* pa = A + (m0 + r) * (size_t)lda + k0 + (kb) + half64 * 32; \
        const __half* pb = B + (n0 + r) * (size_t)ldb + k0 + (kb) + half64 * 32; \
        cpa16(d,      pa);      cpa16(d + 16, pa + 8); \
        cpa16(d + 32, pa + 16); cpa16(d + 48, pa + 24); \
        cpa16(d + 18432,      pb);      cpa16(d + 18432 + 16, pb + 8); \
        cpa16(d + 18432 + 32, pb + 16); cpa16(d + 18432 + 48, pb + 24); \
    } while (0)

    LOAD_STAGE(0, 0); CP_COMMIT();
    if (KT > 1) { LOAD_STAGE(1, BK); CP_COMMIT(); }

    int st = 0;
    for (int kt = 0; kt < KT; kt++) {
        if (kt + 1 >= KT) CP_WAIT(0); else CP_WAIT(1);
        __syncthreads();
        if (kt + 2 < KT) {
            int ns = st + 2; if (ns >= 3) ns -= 3;
            LOAD_STAGE(ns, (kt + 2) * BK);
            CP_COMMIT();
        }

        const uint32_t s = sbase + st * GST;
        const uint32_t arow = s +         (wm * 64 + (lane & 15)) * 144 + (lane >> 4) * 16;
        const uint32_t brow = s + 18432 + (wn * 32 + (lane & 15)) * 144 + (lane >> 4) * 16;

        #pragma unroll
        for (int kh = 0; kh < 4; kh++) {
            uint32_t bf[2][4];
            LDSM4(bf[0], brow + kh * 32);
            LDSM4(bf[1], brow + 2304 + kh * 32);
            #pragma unroll
            for (int mf = 0; mf < 4; mf++) {
                uint32_t ah[4];
                LDSM4(ah, arow + mf * 2304 + kh * 32);
                #pragma unroll
                for (int ng = 0; ng < 2; ng++) {
                    #pragma unroll
                    for (int nn = 0; nn < 2; nn++)
                        MMA16816(acc[mf][ng * 2 + nn], ah, bf[ng][nn], bf[ng][nn + 2]);
                }
            }
        }
        st++; if (st >= 3) st -= 3;
    }

    // epilogue
    #pragma unroll
    for (int mf = 0; mf < 4; mf++) {
        const size_t row = m0 + wm * 64 + mf * 16 + (lane >> 2);
        #pragma unroll
        for (int nf = 0; nf < 4; nf++) {
            const size_t col = n0 + wn * 32 + nf * 8 + (lane & 3) * 2;
            if (MODE == 0) {
                const float b0 = __ldg(bias + col), b1 = __ldg(bias + col + 1);
                __half* C = (__half*)Cv;
                *reinterpret_cast<__half2*>(C + row * (size_t)ldc + col) =
                    __floats2half2_rn(acc[mf][nf][0] + b0, acc[mf][nf][1] + b1);
                *reinterpret_cast<__half2*>(C + (row + 8) * (size_t)ldc + col) =
                    __floats2half2_rn(acc[mf][nf][2] + b0, acc[mf][nf][3] + b1);
            } else {
                float* C = (float*)Cv;
                atomicAdd(C + row * (size_t)ldc + col,           acc[mf][nf][0]);
                atomicAdd(C + row * (size_t)ldc + col + 1,       acc[mf][nf][1]);
                atomicAdd(C + (row + 8) * (size_t)ldc + col,     acc[mf][nf][2]);
                atomicAdd(C + (row + 8) * (size_t)ldc + col + 1, acc[mf][nf][3]);
            }
        }
    }
}

// ============================================================================
// attention: per-token 8x8 head-vs-head softmax. 32 tokens/CTA.
// reads g_QKV fp16 (combined layout), writes g_Oh fp16 [t][2048]
// ============================================================================
#define AP 33
#define ATT_SMEM ((256 * AP * 2 + 2048) * 4)

__global__ void __launch_bounds__(256, 2) attn_kernel() {
    extern __shared__ float sm[];
    float* sQ = sm;
    float* sK = sm + 256 * AP;
    float* sP = sm + 512 * AP;
    const int tid = threadIdx.x;
    const int g0 = blockIdx.x * 32;
    const int lt = tid >> 3, lh = tid & 7;

    float accL[HEADS];
    #pragma unroll
    for (int g = 0; g < HEADS; g++) accL[g] = 0.f;

    for (int dc = 0; dc < 8; dc++) {
        for (int i = tid; i < 4096; i += 256) {
            int t = i >> 7, c = (i & 127) * 2;
            int j = (c >> 5) * DIN + dc * 32 + (c & 31);
            size_t base = (size_t)(g0 + t) * NQKV + j;
            float2 qf = __half22float2(*reinterpret_cast<const __half2*>(g_QKV + base));
            float2 kf = __half22float2(*reinterpret_cast<const __half2*>(g_QKV + base + DH));
            sQ[c * AP + t] = qf.x; sQ[(c + 1) * AP + t] = qf.y;
            sK[c * AP + t] = kf.x; sK[(c + 1) * AP + t] = kf.y;
        }
        __syncthreads();
        #pragma unroll 4
        for (int d2 = 0; d2 < 32; d2++) {
            float qv = sQ[(lh * 32 + d2) * AP + lt];
            #pragma unroll
            for (int g = 0; g < HEADS; g++)
                accL[g] = fmaf(qv, sK[(g * 32 + d2) * AP + lt], accL[g]);
        }
        __syncthreads();
    }
    {
        const float scale = 0.0625f;
        float m = -3.4e38f;
        #pragma unroll
        for (int g = 0; g < HEADS; g++) { accL[g] *= scale; m = fmaxf(m, accL[g]); }
        float s = 0.f;
        #pragma unroll
        for (int g = 0; g < HEADS; g++) { accL[g] = __expf(accL[g] - m); s += accL[g]; }
        float inv = 1.f / s;
        #pragma unroll
        for (int g = 0; g < HEADS; g++)
            sP[(lt * HEADS + lh) * HEADS + g] = accL[g] * inv;
    }
    const int head = tid >> 5, dd = tid & 31;
    for (int dc = 0; dc < 8; dc++) {
        for (int i = tid; i < 4096; i += 256) {
            int t = i >> 7, c = (i & 127) * 2;
            int j = (c >> 5) * DIN + dc * 32 + (c & 31);
            float2 vf = __half22float2(*reinterpret_cast<const __half2*>(
                g_QKV + (size_t)(g0 + t) * NQKV + 2 * DH + j));
            sK[c * AP + t] = vf.x; sK[(c + 1) * AP + t] = vf.y;
        }
        __syncthreads();
        const int j = head * DIN + dc * 32 + dd;
        #pragma unroll 4
        for (int t = 0; t < 32; t++) {
            const float* pp = sP + (t * HEADS + head) * HEADS;
            float o = 0.f;
            #pragma unroll
            for (int g = 0; g < HEADS; g++)
                o = fmaf(pp[g], sK[(g * 32 + dd) * AP + t], o);
            g_Oh[(size_t)(g0 + t) * DH + j] = __float2half_rn(o);
        }
        __syncthreads();
    }
}

// ============================================================================
extern "C" void kernel_launch(void* const* d_in, const int* in_sizes, int n_in,
                              void* d_out, int out_size) {
    const float* x  = (const float*)d_in[0];
    const float* Wq = (const float*)d_in[1];
    const float* bq = (const float*)d_in[2];
    const float* Wk = (const float*)d_in[3];
    const float* bk = (const float*)d_in[4];
    const float* Wv = (const float*)d_in[5];
    const float* bv = (const float*)d_in[6];
    const float* Wo = (const float*)d_in[7];
    const float* bo = (const float*)d_in[8];
    float* out = (float*)d_out;

    cudaFuncSetAttribute(hgemm<0>, cudaFuncAttributeMaxDynamicSharedMemorySize, GSMEM);
    cudaFuncSetAttribute(hgemm<2>, cudaFuncAttributeMaxDynamicSharedMemorySize, GSMEM);
    cudaFuncSetAttribute(attn_kernel, cudaFuncAttributeMaxDynamicSharedMemorySize, ATT_SMEM);

    __half *Xh, *QKV, *Oh, *Wqkv, *Wod;
    float *bqkv;
    cudaGetSymbolAddress((void**)&Xh, g_Xh);
    cudaGetSymbolAddress((void**)&QKV, g_QKV);
    cudaGetSymbolAddress((void**)&Oh, g_Oh);
    cudaGetSymbolAddress((void**)&Wqkv, g_Wqkv);
    cudaGetSymbolAddress((void**)&Wod, g_Wo);
    cudaGetSymbolAddress((void**)&bqkv, g_bqkv);

    // prep
    xconv<<<4096, 256>>>((const float4*)x);
    wconv_all<<<dim3(128, 4), 256>>>(Wq, Wk, Wv, Wo, bq, bk, bv);

    // fused QKV projection: M=16384, N=6144, K=256
    dim3 g1(TOK / 128, NQKV / 128, 1);
    hgemm<0><<<g1, 256, GSMEM>>>(Xh, DIN, Wqkv, DIN, bqkv, QKV, NQKV, DIN);

    // attention
    attn_kernel<<<TOK / 32, 256, ATT_SMEM>>>();

    // out-proj: M=16384, N=256, K=2048 split-K x2, atomic accumulate onto bias
    biasfill<<<(TOK * DIN / 4) / 256, 256>>>(out, bo);
    dim3 g2(TOK / 128, DIN / 128, 2);
    hgemm<2><<<g2, 256, GSMEM>>>(Oh, DH, Wod, DH, nullptr, out, DIN, DH / 2);
}

// round 12
// speedup vs baseline: 1.1134x; 1.1134x over previous
#include <cuda_runtime.h>
#include <cuda_fp16.h>
#include <cstdint>

#define TOK   16384
#define DIN   256
#define DH    2048
#define HEADS 8

// ---------------- device scratch ----------------
__device__ __half g_Xh[(size_t)TOK * DIN];
__device__ __half g_Qh[(size_t)TOK * DH];
__device__ __half g_Kh[(size_t)TOK * DH];
__device__ __half g_Vh[(size_t)TOK * DH];
__device__ __half g_Oh[(size_t)TOK * DH];
__device__ __half g_Wq[DH * DIN];      // [n][k]
__device__ __half g_Wk[DH * DIN];
__device__ __half g_Wv[DH * DIN];
__device__ __half g_Wo[DIN * DH];      // Wo^T [n=256][k=2048]

// ---------------- helpers ----------------
__device__ __forceinline__ uint32_t smem_u32(const void* p) {
    uint32_t a;
    asm("{ .reg .u64 t; cvta.to.shared.u64 t, %1; cvt.u32.u64 %0, t; }" : "=r"(a) : "l"(p));
    return a;
}
__device__ __forceinline__ void cpa16(uint32_t dst, const void* src) {
    asm volatile("cp.async.cg.shared.global [%0], [%1], 16;" :: "r"(dst), "l"(src));
}
#define CP_COMMIT() asm volatile("cp.async.commit_group;" ::: "memory")
#define CP_WAIT(n)  asm volatile("cp.async.wait_group %0;" :: "n"(n) : "memory")

#define LDSM4(r, a) asm volatile( \
    "ldmatrix.sync.aligned.m8n8.x4.shared.b16 {%0,%1,%2,%3}, [%4];" \
    : "=r"((r)[0]), "=r"((r)[1]), "=r"((r)[2]), "=r"((r)[3]) : "r"(a))

#define MMA16816(c, a, b0, b1) asm volatile( \
    "mma.sync.aligned.m16n8k16.row.col.f32.f16.f16.f32 " \
    "{%0,%1,%2,%3}, {%4,%5,%6,%7}, {%8,%9}, {%0,%1,%2,%3};" \
    : "+f"((c)[0]), "+f"((c)[1]), "+f"((c)[2]), "+f"((c)[3]) \
    : "r"((a)[0]), "r"((a)[1]), "r"((a)[2]), "r"((a)[3]), "r"(b0), "r"(b1))

// packed fp32x2 FMA (B300 FFMA2)
__device__ __forceinline__ unsigned long long fma2(unsigned long long a,
                                                   unsigned long long b,
                                                   unsigned long long c) {
    unsigned long long d;
    asm("fma.rn.f32x2 %0, %1, %2, %3;" : "=l"(d) : "l"(a), "l"(b), "l"(c));
    return d;
}
__device__ __forceinline__ unsigned long long pack2(float x, float y) {
    unsigned long long r;
    asm("mov.b64 %0, {%1, %2};" : "=l"(r) : "f"(x), "f"(y));
    return r;
}
__device__ __forceinline__ void unpack2(unsigned long long v, float& x, float& y) {
    asm("mov.b64 {%0, %1}, %2;" : "=f"(x), "=f"(y) : "l"(v));
}

// ============================================================================
// X convert: fp32 -> fp16
// ============================================================================
__global__ void xconv(const float4* __restrict__ x) {
    size_t i = (size_t)blockIdx.x * blockDim.x + threadIdx.x;
    float4 f = x[i];
    __half2* p = reinterpret_cast<__half2*>(g_Xh) + 2 * i;
    p[0] = __floats2half2_rn(f.x, f.y);
    p[1] = __floats2half2_rn(f.z, f.w);
}

// ============================================================================
// fused weight transpose: W[K][N] -> out[N][K] fp16
// ============================================================================
__global__ void wconv_all(const float* __restrict__ Wq, const float* __restrict__ Wk,
                          const float* __restrict__ Wv, const float* __restrict__ Wo) {
    __shared__ float s[64][65];
    const int which = blockIdx.y;
    const float* W; __half* oh; int K, N;
    if (which == 0)      { W = Wq; oh = g_Wq; K = DIN; N = DH; }
    else if (which == 1) { W = Wk; oh = g_Wk; K = DIN; N = DH; }
    else if (which == 2) { W = Wv; oh = g_Wv; K = DIN; N = DH; }
    else                 { W = Wo; oh = g_Wo; K = DH;  N = DIN; }
    const int nt = N / 64;
    const int n0 = (blockIdx.x % nt) * 64, k0 = (blockIdx.x / nt) * 64;
    const int tx = threadIdx.x & 63, ty = threadIdx.x >> 6;
    for (int r = ty; r < 64; r += 4)
        s[r][tx] = W[(size_t)(k0 + r) * N + n0 + tx];
    __syncthreads();
    for (int r = ty; r < 64; r += 4)
        oh[(size_t)(n0 + r) * K + k0 + tx] = __float2half_rn(s[tx][r]);
}

// ============================================================================
// bias prefill for split-K output: out[t][c] = bo[c]  (4096 blocks x 256)
// ============================================================================
__global__ void biasfill(float* __restrict__ out, const float* __restrict__ bo) {
    __shared__ float4 sb[64];
    if (threadIdx.x < 64) sb[threadIdx.x] = ((const float4*)bo)[threadIdx.x];
    __syncthreads();
    size_t i = (size_t)blockIdx.x * blockDim.x + threadIdx.x;
    ((float4*)out)[i] = sb[i & 63];
}

// ============================================================================
// fp16 TN GEMM (R9-proven config): CTA 128x128, 8 warps, BK=32, 4-stage.
// MODE 0: half out + bias.  MODE 2: float atomicAdd (bias prefilled).
// ============================================================================
#define GST   20480
#define GSMEM (4 * GST)

template <int MODE>
__global__ void __launch_bounds__(256, 2)
hgemm(const __half* __restrict__ A, int lda,
      const __half* __restrict__ B, int ldb,
      const float* __restrict__ bias, void* __restrict__ Cv, int ldc, int K)
{
    extern __shared__ char smem[];
    const uint32_t sbase = smem_u32(smem);
    const int tid = threadIdx.x, lane = tid & 31, wid = tid >> 5;
    const int wm = wid >> 2, wn = wid & 3;
    const size_t m0 = (size_t)blockIdx.x * 128;
    const size_t n0 = (size_t)blockIdx.y * 128;
    const size_t k0 = (size_t)blockIdx.z * K;

    float acc[4][4][4];
    #pragma unroll
    for (int a = 0; a < 4; a++)
        #pragma unroll
        for (int b = 0; b < 4; b++)
            #pragma unroll
            for (int c = 0; c < 4; c++) acc[a][b][c] = 0.f;

    const int r = tid >> 1;
    const int cc0 = (tid & 1) * 2;
    const int KT = K / 32;

    #define LOAD_STAGE(s, kb) do { \
        uint32_t d = sbase + (s) * GST; \
        const __half* pa = A + (m0 + r) * (size_t)lda + k0 + (kb); \
        const __half* pb = B + (n0 + r) * (size_t)ldb + k0 + (kb); \
        cpa16(d +         r * 80 + cc0 * 16,       pa + cc0 * 8); \
        cpa16(d +         r * 80 + (cc0 + 1) * 16, pa + (cc0 + 1) * 8); \
        cpa16(d + 10240 + r * 80 + cc0 * 16,       pb + cc0 * 8); \
        cpa16(d + 10240 + r * 80 + (cc0 + 1) * 16, pb + (cc0 + 1) * 8); \
    } while (0)

    LOAD_STAGE(0, 0); CP_COMMIT();
    if (KT > 1) { LOAD_STAGE(1, 32); CP_COMMIT(); }
    if (KT > 2) { LOAD_STAGE(2, 64); CP_COMMIT(); }

    for (int kt = 0; kt < KT; kt++) {
        if (kt + 1 >= KT)      CP_WAIT(0);
        else if (kt + 2 >= KT) CP_WAIT(1);
        else                   CP_WAIT(2);
        __syncthreads();
        if (kt + 3 < KT) { LOAD_STAGE((kt + 3) & 3, (kt + 3) * 32); CP_COMMIT(); }

        const uint32_t s = sbase + (kt & 3) * GST;
        const uint32_t arow = s +         (wm * 64 + (lane & 15)) * 80 + (lane >> 4) * 16;
        const uint32_t brow = s + 10240 + (wn * 32 + (lane & 15)) * 80 + (lane >> 4) * 16;

        #pragma unroll
        for (int kh = 0; kh < 2; kh++) {
            uint32_t bf[2][4];
            LDSM4(bf[0], brow + kh * 32);
            LDSM4(bf[1], brow + 1280 + kh * 32);
            #pragma unroll
            for (int mf = 0; mf < 4; mf++) {
                uint32_t ah[4];
                LDSM4(ah, arow + mf * 1280 + kh * 32);
                #pragma unroll
                for (int ng = 0; ng < 2; ng++) {
                    #pragma unroll
                    for (int nn = 0; nn < 2; nn++)
                        MMA16816(acc[mf][ng * 2 + nn], ah, bf[ng][nn], bf[ng][nn + 2]);
                }
            }
        }
    }

    #pragma unroll
    for (int mf = 0; mf < 4; mf++) {
        const size_t row = m0 + wm * 64 + mf * 16 + (lane >> 2);
        #pragma unroll
        for (int nf = 0; nf < 4; nf++) {
            const size_t col = n0 + wn * 32 + nf * 8 + (lane & 3) * 2;
            if (MODE == 0) {
                const float b0 = __ldg(bias + col), b1 = __ldg(bias + col + 1);
                __half* C = (__half*)Cv;
                *reinterpret_cast<__half2*>(C + row * (size_t)ldc + col) =
                    __floats2half2_rn(acc[mf][nf][0] + b0, acc[mf][nf][1] + b1);
                *reinterpret_cast<__half2*>(C + (row + 8) * (size_t)ldc + col) =
                    __floats2half2_rn(acc[mf][nf][2] + b0, acc[mf][nf][3] + b1);
            } else {
                float* C = (float*)Cv;
                atomicAdd(C + row * (size_t)ldc + col,           acc[mf][nf][0]);
                atomicAdd(C + row * (size_t)ldc + col + 1,       acc[mf][nf][1]);
                atomicAdd(C + (row + 8) * (size_t)ldc + col,     acc[mf][nf][2]);
                atomicAdd(C + (row + 8) * (size_t)ldc + col + 1, acc[mf][nf][3]);
            }
        }
    }
}

// ============================================================================
// attention v2: 4 tokens/CTA, 256 threads, native-layout fp32 smem.
// layout per array: [t][h][d] with head pitch 258 floats, token pitch 2064.
// thread roles: logits = one (t,h,g) pair; O-phase = (t, 64 float2 columns).
// smem: Q(0) K(8256) V(16512) P(24768) floats; total 25024 f = 100096 B.
// ============================================================================
#define ATP 2064            // token pitch (floats)
#define AHP 258             // head pitch (floats)
#define ATT_SMEM (25024 * 4)

__global__ void __launch_bounds__(256, 2) attn_kernel() {
    extern __shared__ float sm[];
    const int tid = threadIdx.x;
    const int g0 = blockIdx.x * 4;

    // ---- load + convert: Q/K/V, 4 tokens = 3 arrays x 4 tokens x 256 uint4 chunks
    for (int i = tid; i < 3072; i += 256) {
        int c16 = i & 255;                 // uint4 chunk within token-array
        int tt  = (i >> 8) & 3;
        int arr = i >> 10;                 // 0=Q 1=K 2=V
        const __half* sp = (arr == 0) ? g_Qh : (arr == 1) ? g_Kh : g_Vh;
        uint4 raw = *reinterpret_cast<const uint4*>(sp + (size_t)(g0 + tt) * DH + c16 * 8);
        int h = c16 >> 5, rr = c16 & 31;
        float2* dst = reinterpret_cast<float2*>(sm + arr * 8256 + tt * ATP + h * AHP + rr * 8);
        const __half2* hp = reinterpret_cast<const __half2*>(&raw);
        dst[0] = __half22float2(hp[0]);
        dst[1] = __half22float2(hp[1]);
        dst[2] = __half22float2(hp[2]);
        dst[3] = __half22float2(hp[3]);
    }
    __syncthreads();

    // ---- logits: thread = (t, h, g); 128 FFMA2 over d
    const int t  = tid >> 6;
    const int hg = tid & 63;
    const int h  = hg >> 3, g = hg & 7;
    {
        const unsigned long long* q8 =
            reinterpret_cast<const unsigned long long*>(sm + t * ATP + h * AHP);
        const unsigned long long* k8 =
            reinterpret_cast<const unsigned long long*>(sm + 8256 + t * ATP + g * AHP);
        unsigned long long acc = 0ull;
        #pragma unroll 8
        for (int j = 0; j < 128; j++)
            acc = fma2(q8[j], k8[j], acc);
        float lo, hi; unpack2(acc, lo, hi);
        float L = (lo + hi) * 0.0625f;
        // softmax over g: 8-lane segments
        float m = L;
        m = fmaxf(m, __shfl_xor_sync(0xffffffffu, m, 1, 8));
        m = fmaxf(m, __shfl_xor_sync(0xffffffffu, m, 2, 8));
        m = fmaxf(m, __shfl_xor_sync(0xffffffffu, m, 4, 8));
        float e = __expf(L - m);
        float s = e;
        s += __shfl_xor_sync(0xffffffffu, s, 1, 8);
        s += __shfl_xor_sync(0xffffffffu, s, 2, 8);
        s += __shfl_xor_sync(0xffffffffu, s, 4, 8);
        sm[24768 + t * 64 + h * 8 + g] = e / s;
    }
    __syncthreads();

    // ---- O = P @ V: thread = (t, dx); 16 x 8 FFMA2
    const int dx = tid & 63;
    const float* pbase = sm + 24768 + t * 64;
    #pragma unroll 4
    for (int dc = 0; dc < 16; dc++) {
        int d2o = dc * 64 + dx;            // float2 output index 0..1023
        int hh = d2o >> 7, dl = d2o & 127;
        const float* pp = pbase + hh * 8;
        unsigned long long o = 0ull;
        #pragma unroll
        for (int gg = 0; gg < 8; gg++) {
            float p = pp[gg];
            unsigned long long v = *reinterpret_cast<const unsigned long long*>(
                sm + 16512 + t * ATP + gg * AHP + dl * 2);
            o = fma2(v, pack2(p, p), o);
        }
        float o0, o1; unpack2(o, o0, o1);
        *reinterpret_cast<__half2*>(g_Oh + (size_t)(g0 + t) * DH + d2o * 2) =
            __floats2half2_rn(o0, o1);
    }
}

// ============================================================================
extern "C" void kernel_launch(void* const* d_in, const int* in_sizes, int n_in,
                              void* d_out, int out_size) {
    const float* x  = (const float*)d_in[0];
    const float* Wq = (const float*)d_in[1];
    const float* bq = (const float*)d_in[2];
    const float* Wk = (const float*)d_in[3];
    const float* bk = (const float*)d_in[4];
    const float* Wv = (const float*)d_in[5];
    const float* bv = (const float*)d_in[6];
    const float* Wo = (const float*)d_in[7];
    const float* bo = (const float*)d_in[8];
    float* out = (float*)d_out;

    cudaFuncSetAttribute(hgemm<0>, cudaFuncAttributeMaxDynamicSharedMemorySize, GSMEM);
    cudaFuncSetAttribute(hgemm<2>, cudaFuncAttributeMaxDynamicSharedMemorySize, GSMEM);
    cudaFuncSetAttribute(attn_kernel, cudaFuncAttributeMaxDynamicSharedMemorySize, ATT_SMEM);

    __half *Xh, *Qh, *Kh, *Vh, *Oh, *Wqd, *Wkd, *Wvd, *Wod;
    cudaGetSymbolAddress((void**)&Xh, g_Xh);
    cudaGetSymbolAddress((void**)&Qh, g_Qh);
    cudaGetSymbolAddress((void**)&Kh, g_Kh);
    cudaGetSymbolAddress((void**)&Vh, g_Vh);
    cudaGetSymbolAddress((void**)&Oh, g_Oh);
    cudaGetSymbolAddress((void**)&Wqd, g_Wq); cudaGetSymbolAddress((void**)&Wkd, g_Wk);
    cudaGetSymbolAddress((void**)&Wvd, g_Wv); cudaGetSymbolAddress((void**)&Wod, g_Wo);

    // prep
    xconv<<<4096, 256>>>((const float4*)x);
    wconv_all<<<dim3(128, 4), 256>>>(Wq, Wk, Wv, Wo);

    // QKV projections (R9-proven): M=16384, N=2048, K=256
    dim3 g1(TOK / 128, DH / 128, 1);
    hgemm<0><<<g1, 256, GSMEM>>>(Xh, DIN, Wqd, DIN, bq, Qh, DH, DIN);
    hgemm<0><<<g1, 256, GSMEM>>>(Xh, DIN, Wkd, DIN, bk, Kh, DH, DIN);
    hgemm<0><<<g1, 256, GSMEM>>>(Xh, DIN, Wvd, DIN, bv, Vh, DH, DIN);

    // attention v2
    attn_kernel<<<TOK / 4, 256, ATT_SMEM>>>();

    // out-proj: split-K x2, atomic accumulate onto bias
    biasfill<<<(TOK * DIN / 4) / 256, 256>>>(out, bo);
    dim3 g2(TOK / 128, DIN / 128, 2);
    hgemm<2><<<g2, 256, GSMEM>>>(Oh, DH, Wod, DH, nullptr, out, DIN, DH / 2);
}

// round 14
// speedup vs baseline: 1.3109x; 1.1774x over previous
#include <cuda_runtime.h>
#include <cuda_fp16.h>
#include <cstdint>

#define TOK   16384
#define DIN   256
#define DH    2048
#define HEADS 8

// ---------------- device scratch ----------------
__device__ __half g_Xh[(size_t)TOK * DIN];
__device__ __half g_Qh[(size_t)TOK * DH];
__device__ __half g_Kh[(size_t)TOK * DH];
__device__ __half g_Vh[(size_t)TOK * DH];
__device__ __half g_Oh[(size_t)TOK * DH];
__device__ __half g_Wq[DH * DIN];      // [n][k]
__device__ __half g_Wk[DH * DIN];
__device__ __half g_Wv[DH * DIN];
__device__ __half g_Wo[DIN * DH];      // Wo^T [n=256][k=2048]

// ---------------- helpers ----------------
__device__ __forceinline__ uint32_t smem_u32(const void* p) {
    uint32_t a;
    asm("{ .reg .u64 t; cvta.to.shared.u64 t, %1; cvt.u32.u64 %0, t; }" : "=r"(a) : "l"(p));
    return a;
}
__device__ __forceinline__ void cpa16(uint32_t dst, const void* src) {
    asm volatile("cp.async.cg.shared.global [%0], [%1], 16;" :: "r"(dst), "l"(src));
}
#define CP_COMMIT() asm volatile("cp.async.commit_group;" ::: "memory")
#define CP_WAIT(n)  asm volatile("cp.async.wait_group %0;" :: "n"(n) : "memory")

#define LDSM4(r, a) asm volatile( \
    "ldmatrix.sync.aligned.m8n8.x4.shared.b16 {%0,%1,%2,%3}, [%4];" \
    : "=r"((r)[0]), "=r"((r)[1]), "=r"((r)[2]), "=r"((r)[3]) : "r"(a))

#define MMA16816(c, a, b0, b1) asm volatile( \
    "mma.sync.aligned.m16n8k16.row.col.f32.f16.f16.f32 " \
    "{%0,%1,%2,%3}, {%4,%5,%6,%7}, {%8,%9}, {%0,%1,%2,%3};" \
    : "+f"((c)[0]), "+f"((c)[1]), "+f"((c)[2]), "+f"((c)[3]) \
    : "r"((a)[0]), "r"((a)[1]), "r"((a)[2]), "r"((a)[3]), "r"(b0), "r"(b1))

// packed fp32x2 FMA (B300 FFMA2)
__device__ __forceinline__ unsigned long long fma2(unsigned long long a,
                                                   unsigned long long b,
                                                   unsigned long long c) {
    unsigned long long d;
    asm("fma.rn.f32x2 %0, %1, %2, %3;" : "=l"(d) : "l"(a), "l"(b), "l"(c));
    return d;
}
__device__ __forceinline__ unsigned long long pack2(float x, float y) {
    unsigned long long r;
    asm("mov.b64 %0, {%1, %2};" : "=l"(r) : "f"(x), "f"(y));
    return r;
}
__device__ __forceinline__ void unpack2(unsigned long long v, float& x, float& y) {
    asm("mov.b64 {%0, %1}, %2;" : "=f"(x), "=f"(y) : "l"(v));
}
__device__ __forceinline__ unsigned long long h2_to_f2(uint32_t h2) {
    float2 f = __half22float2(*reinterpret_cast<const __half2*>(&h2));
    return pack2(f.x, f.y);
}

// ============================================================================
// X convert: fp32 -> fp16
// ============================================================================
__global__ void xconv(const float4* __restrict__ x) {
    size_t i = (size_t)blockIdx.x * blockDim.x + threadIdx.x;
    float4 f = x[i];
    __half2* p = reinterpret_cast<__half2*>(g_Xh) + 2 * i;
    p[0] = __floats2half2_rn(f.x, f.y);
    p[1] = __floats2half2_rn(f.z, f.w);
}

// ============================================================================
// fused weight transpose: W[K][N] -> out[N][K] fp16
// ============================================================================
__global__ void wconv_all(const float* __restrict__ Wq, const float* __restrict__ Wk,
                          const float* __restrict__ Wv, const float* __restrict__ Wo) {
    __shared__ float s[64][65];
    const int which = blockIdx.y;
    const float* W; __half* oh; int K, N;
    if (which == 0)      { W = Wq; oh = g_Wq; K = DIN; N = DH; }
    else if (which == 1) { W = Wk; oh = g_Wk; K = DIN; N = DH; }
    else if (which == 2) { W = Wv; oh = g_Wv; K = DIN; N = DH; }
    else                 { W = Wo; oh = g_Wo; K = DH;  N = DIN; }
    const int nt = N / 64;
    const int n0 = (blockIdx.x % nt) * 64, k0 = (blockIdx.x / nt) * 64;
    const int tx = threadIdx.x & 63, ty = threadIdx.x >> 6;
    for (int r = ty; r < 64; r += 4)
        s[r][tx] = W[(size_t)(k0 + r) * N + n0 + tx];
    __syncthreads();
    for (int r = ty; r < 64; r += 4)
        oh[(size_t)(n0 + r) * K + k0 + tx] = __float2half_rn(s[tx][r]);
}

// ============================================================================
// bias prefill for split-K output: out[t][c] = bo[c]  (4096 blocks x 256)
// ============================================================================
__global__ void biasfill(float* __restrict__ out, const float* __restrict__ bo) {
    __shared__ float4 sb[64];
    if (threadIdx.x < 64) sb[threadIdx.x] = ((const float4*)bo)[threadIdx.x];
    __syncthreads();
    size_t i = (size_t)blockIdx.x * blockDim.x + threadIdx.x;
    ((float4*)out)[i] = sb[i & 63];
}

// ============================================================================
// fp16 TN GEMM (R9-proven config): CTA 128x128, 8 warps, BK=32, 4-stage.
// MODE 0: half out + bias.  MODE 2: float atomicAdd (bias prefilled).
// ============================================================================
#define GST   20480
#define GSMEM (4 * GST)

template <int MODE>
__global__ void __launch_bounds__(256, 2)
hgemm(const __half* __restrict__ A, int lda,
      const __half* __restrict__ B, int ldb,
      const float* __restrict__ bias, void* __restrict__ Cv, int ldc, int K)
{
    extern __shared__ char smem[];
    const uint32_t sbase = smem_u32(smem);
    const int tid = threadIdx.x, lane = tid & 31, wid = tid >> 5;
    const int wm = wid >> 2, wn = wid & 3;
    const size_t m0 = (size_t)blockIdx.x * 128;
    const size_t n0 = (size_t)blockIdx.y * 128;
    const size_t k0 = (size_t)blockIdx.z * K;

    float acc[4][4][4];
    #pragma unroll
    for (int a = 0; a < 4; a++)
        #pragma unroll
        for (int b = 0; b < 4; b++)
            #pragma unroll
            for (int c = 0; c < 4; c++) acc[a][b][c] = 0.f;

    const int r = tid >> 1;
    const int cc0 = (tid & 1) * 2;
    const int KT = K / 32;

    #define LOAD_STAGE(s, kb) do { \
        uint32_t d = sbase + (s) * GST; \
        const __half* pa = A + (m0 + r) * (size_t)lda + k0 + (kb); \
        const __half* pb = B + (n0 + r) * (size_t)ldb + k0 + (kb); \
        cpa16(d +         r * 80 + cc0 * 16,       pa + cc0 * 8); \
        cpa16(d +         r * 80 + (cc0 + 1) * 16, pa + (cc0 + 1) * 8); \
        cpa16(d + 10240 + r * 80 + cc0 * 16,       pb + cc0 * 8); \
        cpa16(d + 10240 + r * 80 + (cc0 + 1) * 16, pb + (cc0 + 1) * 8); \
    } while (0)

    LOAD_STAGE(0, 0); CP_COMMIT();
    if (KT > 1) { LOAD_STAGE(1, 32); CP_COMMIT(); }
    if (KT > 2) { LOAD_STAGE(2, 64); CP_COMMIT(); }

    for (int kt = 0; kt < KT; kt++) {
        if (kt + 1 >= KT)      CP_WAIT(0);
        else if (kt + 2 >= KT) CP_WAIT(1);
        else                   CP_WAIT(2);
        __syncthreads();
        if (kt + 3 < KT) { LOAD_STAGE((kt + 3) & 3, (kt + 3) * 32); CP_COMMIT(); }

        const uint32_t s = sbase + (kt & 3) * GST;
        const uint32_t arow = s +         (wm * 64 + (lane & 15)) * 80 + (lane >> 4) * 16;
        const uint32_t brow = s + 10240 + (wn * 32 + (lane & 15)) * 80 + (lane >> 4) * 16;

        #pragma unroll
        for (int kh = 0; kh < 2; kh++) {
            uint32_t bf[2][4];
            LDSM4(bf[0], brow + kh * 32);
            LDSM4(bf[1], brow + 1280 + kh * 32);
            #pragma unroll
            for (int mf = 0; mf < 4; mf++) {
                uint32_t ah[4];
                LDSM4(ah, arow + mf * 1280 + kh * 32);
                #pragma unroll
                for (int ng = 0; ng < 2; ng++) {
                    #pragma unroll
                    for (int nn = 0; nn < 2; nn++)
                        MMA16816(acc[mf][ng * 2 + nn], ah, bf[ng][nn], bf[ng][nn + 2]);
                }
            }
        }
    }

    #pragma unroll
    for (int mf = 0; mf < 4; mf++) {
        const size_t row = m0 + wm * 64 + mf * 16 + (lane >> 2);
        #pragma unroll
        for (int nf = 0; nf < 4; nf++) {
            const size_t col = n0 + wn * 32 + nf * 8 + (lane & 3) * 2;
            if (MODE == 0) {
                const float b0 = __ldg(bias + col), b1 = __ldg(bias + col + 1);
                __half* C = (__half*)Cv;
                *reinterpret_cast<__half2*>(C + row * (size_t)ldc + col) =
                    __floats2half2_rn(acc[mf][nf][0] + b0, acc[mf][nf][1] + b1);
                *reinterpret_cast<__half2*>(C + (row + 8) * (size_t)ldc + col) =
                    __floats2half2_rn(acc[mf][nf][2] + b0, acc[mf][nf][3] + b1);
            } else {
                float* C = (float*)Cv;
                atomicAdd(C + row * (size_t)ldc + col,           acc[mf][nf][0]);
                atomicAdd(C + row * (size_t)ldc + col + 1,       acc[mf][nf][1]);
                atomicAdd(C + (row + 8) * (size_t)ldc + col,     acc[mf][nf][2]);
                atomicAdd(C + (row + 8) * (size_t)ldc + col + 1, acc[mf][nf][3]);
            }
        }
    }
}

// ============================================================================
// attention v3: 4 tokens/CTA, 256 threads, fp16 smem, cp.async staging, 3 CTA/SM.
// half layout per array: [t][h][d], head pitch AHPH=264 halves, token pitch
// ATPH=2112 halves; per-array span = 4*ATPH = 8448 halves = 16896 BYTES.
// arrays (half offsets): Q @ 0, K @ 8448, V @ 16896; P fp32 after 25344 halves.
// smem total: 25344*2 + 4*64*4 = 51712 B.
// ============================================================================
#define AHPH 264     // head pitch (halves)
#define ATPH 2112    // token pitch (halves)
#define ARRB 16896   // per-array stride in BYTES (= 4 * ATPH * 2)
#define ATT_SMEM 51712

__global__ void __launch_bounds__(256, 3) attn_kernel() {
    extern __shared__ __half smh[];
    float* Pf = reinterpret_cast<float*>(smh + 25344);
    const uint32_t sb = smem_u32(smh);
    const int tid = threadIdx.x;
    const int g0 = blockIdx.x * 4;

    // ---- stage Q/K/V via cp.async: 3 arrays x 4 tokens x 256 16B-chunks.
    // ALL dst terms in BYTES: arr*ARRB + tt*(ATPH*2) + h*(AHPH*2) + rr*16
    for (int i = tid; i < 3072; i += 256) {
        int c16 = i & 255, tt = (i >> 8) & 3, arr = i >> 10;
        const __half* sp = (arr == 0) ? g_Qh : (arr == 1) ? g_Kh : g_Vh;
        int h = c16 >> 5, rr = c16 & 31;
        uint32_t dst = sb + (uint32_t)(arr * ARRB + tt * (ATPH * 2) + h * (AHPH * 2) + rr * 16);
        cpa16(dst, sp + (size_t)(g0 + tt) * DH + c16 * 8);
    }
    CP_COMMIT(); CP_WAIT(0);
    __syncthreads();

    // ---- logits: thread = (t, h, g); 64 j-steps of 4 halves each
    const int t  = tid >> 6;
    const int hg = tid & 63;
    const int h  = hg >> 3, g = hg & 7;
    {
        const uint2* q4 = reinterpret_cast<const uint2*>(smh + t * ATPH + h * AHPH);
        const uint2* k4 = reinterpret_cast<const uint2*>(smh + 8448 + t * ATPH + g * AHPH);
        unsigned long long acc = 0ull;
        #pragma unroll 8
        for (int j = 0; j < 64; j++) {
            uint2 qw = q4[j], kw = k4[j];
            acc = fma2(h2_to_f2(qw.x), h2_to_f2(kw.x), acc);
            acc = fma2(h2_to_f2(qw.y), h2_to_f2(kw.y), acc);
        }
        float lo, hi; unpack2(acc, lo, hi);
        float L = (lo + hi) * 0.0625f;
        float m = L;
        m = fmaxf(m, __shfl_xor_sync(0xffffffffu, m, 1, 8));
        m = fmaxf(m, __shfl_xor_sync(0xffffffffu, m, 2, 8));
        m = fmaxf(m, __shfl_xor_sync(0xffffffffu, m, 4, 8));
        float e = __expf(L - m);
        float s = e;
        s += __shfl_xor_sync(0xffffffffu, s, 1, 8);
        s += __shfl_xor_sync(0xffffffffu, s, 2, 8);
        s += __shfl_xor_sync(0xffffffffu, s, 4, 8);
        Pf[t * 64 + h * 8 + g] = e / s;
    }
    __syncthreads();

    // ---- O = P @ V: thread = (t, dx); 8 chunks of 4 floats
    const int dx = tid & 63;
    const float* pbase = Pf + t * 64;
    #pragma unroll
    for (int dc = 0; dc < 8; dc++) {
        int c = dc * 64 + dx;              // 4-float chunk index 0..511
        int hh = c >> 6, dl = (c & 63) * 4;
        const float* pp = pbase + hh * 8;
        unsigned long long o01 = 0ull, o23 = 0ull;
        #pragma unroll
        for (int gg = 0; gg < 8; gg++) {
            float p = pp[gg];
            unsigned long long p2 = pack2(p, p);
            uint2 vw = *reinterpret_cast<const uint2*>(smh + 16896 + t * ATPH + gg * AHPH + dl);
            o01 = fma2(h2_to_f2(vw.x), p2, o01);
            o23 = fma2(h2_to_f2(vw.y), p2, o23);
        }
        float a0, a1, a2, a3;
        unpack2(o01, a0, a1); unpack2(o23, a2, a3);
        uint2 pk;
        __half2 h01 = __floats2half2_rn(a0, a1), h23 = __floats2half2_rn(a2, a3);
        pk.x = *reinterpret_cast<uint32_t*>(&h01);
        pk.y = *reinterpret_cast<uint32_t*>(&h23);
        *reinterpret_cast<uint2*>(g_Oh + (size_t)(g0 + t) * DH + c * 4) = pk;
    }
}

// ============================================================================
extern "C" void kernel_launch(void* const* d_in, const int* in_sizes, int n_in,
                              void* d_out, int out_size) {
    const float* x  = (const float*)d_in[0];
    const float* Wq = (const float*)d_in[1];
    const float* bq = (const float*)d_in[2];
    const float* Wk = (const float*)d_in[3];
    const float* bk = (const float*)d_in[4];
    const float* Wv = (const float*)d_in[5];
    const float* bv = (const float*)d_in[6];
    const float* Wo = (const float*)d_in[7];
    const float* bo = (const float*)d_in[8];
    float* out = (float*)d_out;

    cudaFuncSetAttribute(hgemm<0>, cudaFuncAttributeMaxDynamicSharedMemorySize, GSMEM);
    cudaFuncSetAttribute(hgemm<2>, cudaFuncAttributeMaxDynamicSharedMemorySize, GSMEM);
    cudaFuncSetAttribute(attn_kernel, cudaFuncAttributeMaxDynamicSharedMemorySize, ATT_SMEM);

    __half *Xh, *Qh, *Kh, *Vh, *Oh, *Wqd, *Wkd, *Wvd, *Wod;
    cudaGetSymbolAddress((void**)&Xh, g_Xh);
    cudaGetSymbolAddress((void**)&Qh, g_Qh);
    cudaGetSymbolAddress((void**)&Kh, g_Kh);
    cudaGetSymbolAddress((void**)&Vh, g_Vh);
    cudaGetSymbolAddress((void**)&Oh, g_Oh);
    cudaGetSymbolAddress((void**)&Wqd, g_Wq); cudaGetSymbolAddress((void**)&Wkd, g_Wk);
    cudaGetSymbolAddress((void**)&Wvd, g_Wv); cudaGetSymbolAddress((void**)&Wod, g_Wo);

    // prep
    xconv<<<4096, 256>>>((const float4*)x);
    wconv_all<<<dim3(128, 4), 256>>>(Wq, Wk, Wv, Wo);

    // QKV projections (R9-proven): M=16384, N=2048, K=256
    dim3 g1(TOK / 128, DH / 128, 1);
    hgemm<0><<<g1, 256, GSMEM>>>(Xh, DIN, Wqd, DIN, bq, Qh, DH, DIN);
    hgemm<0><<<g1, 256, GSMEM>>>(Xh, DIN, Wkd, DIN, bk, Kh, DH, DIN);
    hgemm<0><<<g1, 256, GSMEM>>>(Xh, DIN, Wvd, DIN, bv, Vh, DH, DIN);

    // attention v3
    attn_kernel<<<TOK / 4, 256, ATT_SMEM>>>();

    // out-proj: split-K x2, atomic accumulate onto bias
    biasfill<<<(TOK * DIN / 4) / 256, 256>>>(out, bo);
    dim3 g2(TOK / 128, DIN / 128, 2);
    hgemm<2><<<g2, 256, GSMEM>>>(Oh, DH, Wod, DH, nullptr, out, DIN, DH / 2);
}

// round 15
// speedup vs baseline: 1.4683x; 1.1201x over previous
#include <cuda_runtime.h>
#include <cuda_fp16.h>
#include <cstdint>

#define TOK   16384
#define DIN   256
#define DH    2048
#define HEADS 8

// ---------------- device scratch ----------------
__device__ __half g_Xh[(size_t)TOK * DIN];
__device__ __half g_Qh[(size_t)TOK * DH];
__device__ __half g_Kh[(size_t)TOK * DH];
__device__ __half g_Vh[(size_t)TOK * DH];
__device__ __half g_Oh[(size_t)TOK * DH];
__device__ __half g_Wq[DH * DIN];      // [n][k]
__device__ __half g_Wk[DH * DIN];
__device__ __half g_Wv[DH * DIN];
__device__ __half g_Wo[DIN * DH];      // Wo^T [n=256][k=2048]

// ---------------- helpers ----------------
__device__ __forceinline__ uint32_t smem_u32(const void* p) {
    uint32_t a;
    asm("{ .reg .u64 t; cvta.to.shared.u64 t, %1; cvt.u32.u64 %0, t; }" : "=r"(a) : "l"(p));
    return a;
}
__device__ __forceinline__ void cpa16(uint32_t dst, const void* src) {
    asm volatile("cp.async.cg.shared.global [%0], [%1], 16;" :: "r"(dst), "l"(src));
}
#define CP_COMMIT() asm volatile("cp.async.commit_group;" ::: "memory")
#define CP_WAIT(n)  asm volatile("cp.async.wait_group %0;" :: "n"(n) : "memory")

#define LDSM4(r, a) asm volatile( \
    "ldmatrix.sync.aligned.m8n8.x4.shared.b16 {%0,%1,%2,%3}, [%4];" \
    : "=r"((r)[0]), "=r"((r)[1]), "=r"((r)[2]), "=r"((r)[3]) : "r"(a))

#define MMA16816(c, a, b0, b1) asm volatile( \
    "mma.sync.aligned.m16n8k16.row.col.f32.f16.f16.f32 " \
    "{%0,%1,%2,%3}, {%4,%5,%6,%7}, {%8,%9}, {%0,%1,%2,%3};" \
    : "+f"((c)[0]), "+f"((c)[1]), "+f"((c)[2]), "+f"((c)[3]) \
    : "r"((a)[0]), "r"((a)[1]), "r"((a)[2]), "r"((a)[3]), "r"(b0), "r"(b1))

// packed fp32x2 FMA (B300 FFMA2)
__device__ __forceinline__ unsigned long long fma2(unsigned long long a,
                                                   unsigned long long b,
                                                   unsigned long long c) {
    unsigned long long d;
    asm("fma.rn.f32x2 %0, %1, %2, %3;" : "=l"(d) : "l"(a), "l"(b), "l"(c));
    return d;
}
__device__ __forceinline__ unsigned long long pack2(float x, float y) {
    unsigned long long r;
    asm("mov.b64 %0, {%1, %2};" : "=l"(r) : "f"(x), "f"(y));
    return r;
}
__device__ __forceinline__ void unpack2(unsigned long long v, float& x, float& y) {
    asm("mov.b64 {%0, %1}, %2;" : "=f"(x), "=f"(y) : "l"(v));
}
__device__ __forceinline__ unsigned long long h2_to_f2(uint32_t h2) {
    float2 f = __half22float2(*reinterpret_cast<const __half2*>(&h2));
    return pack2(f.x, f.y);
}

// ============================================================================
// X convert: fp32 -> fp16
// ============================================================================
__global__ void xconv(const float4* __restrict__ x) {
    size_t i = (size_t)blockIdx.x * blockDim.x + threadIdx.x;
    float4 f = x[i];
    __half2* p = reinterpret_cast<__half2*>(g_Xh) + 2 * i;
    p[0] = __floats2half2_rn(f.x, f.y);
    p[1] = __floats2half2_rn(f.z, f.w);
}

// ============================================================================
// fused weight transpose: W[K][N] -> out[N][K] fp16
// ============================================================================
__global__ void wconv_all(const float* __restrict__ Wq, const float* __restrict__ Wk,
                          const float* __restrict__ Wv, const float* __restrict__ Wo) {
    __shared__ float s[64][65];
    const int which = blockIdx.y;
    const float* W; __half* oh; int K, N;
    if (which == 0)      { W = Wq; oh = g_Wq; K = DIN; N = DH; }
    else if (which == 1) { W = Wk; oh = g_Wk; K = DIN; N = DH; }
    else if (which == 2) { W = Wv; oh = g_Wv; K = DIN; N = DH; }
    else                 { W = Wo; oh = g_Wo; K = DH;  N = DIN; }
    const int nt = N / 64;
    const int n0 = (blockIdx.x % nt) * 64, k0 = (blockIdx.x / nt) * 64;
    const int tx = threadIdx.x & 63, ty = threadIdx.x >> 6;
    for (int r = ty; r < 64; r += 4)
        s[r][tx] = W[(size_t)(k0 + r) * N + n0 + tx];
    __syncthreads();
    for (int r = ty; r < 64; r += 4)
        oh[(size_t)(n0 + r) * K + k0 + tx] = __float2half_rn(s[tx][r]);
}

// ============================================================================
// bias prefill for split-K output: out[t][c] = bo[c]  (4096 blocks x 256)
// ============================================================================
__global__ void biasfill(float* __restrict__ out, const float* __restrict__ bo) {
    __shared__ float4 sb[64];
    if (threadIdx.x < 64) sb[threadIdx.x] = ((const float4*)bo)[threadIdx.x];
    __syncthreads();
    size_t i = (size_t)blockIdx.x * blockDim.x + threadIdx.x;
    ((float4*)out)[i] = sb[i & 63];
}

// ============================================================================
// hgemm_ra: A-RESIDENT fp16 TN GEMM for K=256.
// CTA 128x128, 8 warps (2m x 4n), warp tile 64x32.
// A tile (128x256 half, pitch 528B = 67584B) loaded ONCE into smem.
// B streams in PAIRS of k-iters (2 x 10240B super-stage, double buffered).
// One barrier per 2 k-iters (64 MMAs per interval).
// smem = 67584 + 40960 = 108544B  -> 2 CTA/SM.
// ============================================================================
#define RA_APITCH 528
#define RA_BOFF   67584
#define RA_SMEM   (67584 + 40960)

__global__ void __launch_bounds__(256, 2)
hgemm_ra(const __half* __restrict__ A, int lda,
         const __half* __restrict__ B, int ldb,
         const float* __restrict__ bias, __half* __restrict__ C, int ldc)
{
    extern __shared__ char smem[];
    const uint32_t sbase = smem_u32(smem);
    const int tid = threadIdx.x, lane = tid & 31, wid = tid >> 5;
    const int wm = wid >> 2, wn = wid & 3;
    const size_t m0 = (size_t)blockIdx.x * 128;
    const size_t n0 = (size_t)blockIdx.y * 128;

    float acc[4][4][4];
    #pragma unroll
    for (int a = 0; a < 4; a++)
        #pragma unroll
        for (int b = 0; b < 4; b++)
            #pragma unroll
            for (int c = 0; c < 4; c++) acc[a][b][c] = 0.f;

    // ---- load A resident: 4096 16B chunks, 16 per thread ----
    #pragma unroll
    for (int i = 0; i < 16; i++) {
        int c = tid + i * 256;
        int row = c >> 5, k16 = c & 31;
        cpa16(sbase + row * RA_APITCH + k16 * 16, A + (m0 + row) * (size_t)lda + k16 * 8);
    }

    // ---- B pair loader: pair p covers k-iters 2p, 2p+1 (each 128 rows x 64B) ----
    #define RA_LOAD_PAIR(p, ss) do { \
        _Pragma("unroll") \
        for (int i = 0; i < 4; i++) { \
            int c = tid + i * 256;                     /* 0..1023 */ \
            int it = c >> 9, row = (c >> 2) & 127, ch = c & 3; \
            cpa16(sbase + RA_BOFF + (ss) * 20480 + it * 10240 + row * 80 + ch * 16, \
                  B + (n0 + row) * (size_t)ldb + (2 * (p) + it) * 32 + ch * 8); \
        } \
    } while (0)

    RA_LOAD_PAIR(0, 0);
    CP_COMMIT();
    CP_WAIT(0);
    __syncthreads();

    const uint32_t arow0 = sbase + (wm * 64 + (lane & 15)) * RA_APITCH + (lane >> 4) * 16;

    #pragma unroll
    for (int p = 0; p < 4; p++) {            // 4 pairs = 8 k-iters (K=256)
        if (p + 1 < 4) { RA_LOAD_PAIR(p + 1, (p + 1) & 1); CP_COMMIT(); }

        #pragma unroll
        for (int it = 0; it < 2; it++) {
            const int kt = 2 * p + it;
            const uint32_t bs = sbase + RA_BOFF + (p & 1) * 20480 + it * 10240;
            const uint32_t brow = bs + (wn * 32 + (lane & 15)) * 80 + (lane >> 4) * 16;
            const uint32_t arow = arow0 + kt * 64;

            #pragma unroll
            for (int kh = 0; kh < 2; kh++) {
                uint32_t bf[2][4];
                LDSM4(bf[0], brow + kh * 32);
                LDSM4(bf[1], brow + 1280 + kh * 32);
                #pragma unroll
                for (int mf = 0; mf < 4; mf++) {
                    uint32_t ah[4];
                    LDSM4(ah, arow + mf * (16 * RA_APITCH) + kh * 32);
                    #pragma unroll
                    for (int ng = 0; ng < 2; ng++) {
                        #pragma unroll
                        for (int nn = 0; nn < 2; nn++)
                            MMA16816(acc[mf][ng * 2 + nn], ah, bf[ng][nn], bf[ng][nn + 2]);
                    }
                }
            }
        }
        if (p + 1 < 4) { CP_WAIT(0); __syncthreads(); }
    }

    // ---- epilogue: half out + bias ----
    #pragma unroll
    for (int mf = 0; mf < 4; mf++) {
        const size_t row = m0 + wm * 64 + mf * 16 + (lane >> 2);
        #pragma unroll
        for (int nf = 0; nf < 4; nf++) {
            const size_t col = n0 + wn * 32 + nf * 8 + (lane & 3) * 2;
            const float b0 = __ldg(bias + col), b1 = __ldg(bias + col + 1);
            *reinterpret_cast<__half2*>(C + row * (size_t)ldc + col) =
                __floats2half2_rn(acc[mf][nf][0] + b0, acc[mf][nf][1] + b1);
            *reinterpret_cast<__half2*>(C + (row + 8) * (size_t)ldc + col) =
                __floats2half2_rn(acc[mf][nf][2] + b0, acc[mf][nf][3] + b1);
        }
    }
}

// ============================================================================
// streaming fp16 TN GEMM (R9-proven): CTA 128x128, 8 warps, BK=32, 4-stage.
// MODE 2: float atomicAdd epilogue (bias prefilled) for split-K out-proj.
// ============================================================================
#define GST   20480
#define GSMEM (4 * GST)

__global__ void __launch_bounds__(256, 2)
hgemm_sk(const __half* __restrict__ A, int lda,
         const __half* __restrict__ B, int ldb,
         float* __restrict__ C, int ldc, int K)
{
    extern __shared__ char smem[];
    const uint32_t sbase = smem_u32(smem);
    const int tid = threadIdx.x, lane = tid & 31, wid = tid >> 5;
    const int wm = wid >> 2, wn = wid & 3;
    const size_t m0 = (size_t)blockIdx.x * 128;
    const size_t n0 = (size_t)blockIdx.y * 128;
    const size_t k0 = (size_t)blockIdx.z * K;

    float acc[4][4][4];
    #pragma unroll
    for (int a = 0; a < 4; a++)
        #pragma unroll
        for (int b = 0; b < 4; b++)
            #pragma unroll
            for (int c = 0; c < 4; c++) acc[a][b][c] = 0.f;

    const int r = tid >> 1;
    const int cc0 = (tid & 1) * 2;
    const int KT = K / 32;

    #define LOAD_STAGE(s, kb) do { \
        uint32_t d = sbase + (s) * GST; \
        const __half* pa = A + (m0 + r) * (size_t)lda + k0 + (kb); \
        const __half* pb = B + (n0 + r) * (size_t)ldb + k0 + (kb); \
        cpa16(d +         r * 80 + cc0 * 16,       pa + cc0 * 8); \
        cpa16(d +         r * 80 + (cc0 + 1) * 16, pa + (cc0 + 1) * 8); \
        cpa16(d + 10240 + r * 80 + cc0 * 16,       pb + cc0 * 8); \
        cpa16(d + 10240 + r * 80 + (cc0 + 1) * 16, pb + (cc0 + 1) * 8); \
    } while (0)

    LOAD_STAGE(0, 0); CP_COMMIT();
    if (KT > 1) { LOAD_STAGE(1, 32); CP_COMMIT(); }
    if (KT > 2) { LOAD_STAGE(2, 64); CP_COMMIT(); }

    for (int kt = 0; kt < KT; kt++) {
        if (kt + 1 >= KT)      CP_WAIT(0);
        else if (kt + 2 >= KT) CP_WAIT(1);
        else                   CP_WAIT(2);
        __syncthreads();
        if (kt + 3 < KT) { LOAD_STAGE((kt + 3) & 3, (kt + 3) * 32); CP_COMMIT(); }

        const uint32_t s = sbase + (kt & 3) * GST;
        const uint32_t arow = s +         (wm * 64 + (lane & 15)) * 80 + (lane >> 4) * 16;
        const uint32_t brow = s + 10240 + (wn * 32 + (lane & 15)) * 80 + (lane >> 4) * 16;

        #pragma unroll
        for (int kh = 0; kh < 2; kh++) {
            uint32_t bf[2][4];
            LDSM4(bf[0], brow + kh * 32);
            LDSM4(bf[1], brow + 1280 + kh * 32);
            #pragma unroll
            for (int mf = 0; mf < 4; mf++) {
                uint32_t ah[4];
                LDSM4(ah, arow + mf * 1280 + kh * 32);
                #pragma unroll
                for (int ng = 0; ng < 2; ng++) {
                    #pragma unroll
                    for (int nn = 0; nn < 2; nn++)
                        MMA16816(acc[mf][ng * 2 + nn], ah, bf[ng][nn], bf[ng][nn + 2]);
                }
            }
        }
    }

    #pragma unroll
    for (int mf = 0; mf < 4; mf++) {
        const size_t row = m0 + wm * 64 + mf * 16 + (lane >> 2);
        #pragma unroll
        for (int nf = 0; nf < 4; nf++) {
            const size_t col = n0 + wn * 32 + nf * 8 + (lane & 3) * 2;
            atomicAdd(C + row * (size_t)ldc + col,           acc[mf][nf][0]);
            atomicAdd(C + row * (size_t)ldc + col + 1,       acc[mf][nf][1]);
            atomicAdd(C + (row + 8) * (size_t)ldc + col,     acc[mf][nf][2]);
            atomicAdd(C + (row + 8) * (size_t)ldc + col + 1, acc[mf][nf][3]);
        }
    }
}

// ============================================================================
// attention v3 (R14-proven): 4 tokens/CTA, fp16 smem, cp.async, 3 CTA/SM.
// ============================================================================
#define AHPH 264
#define ATPH 2112
#define ARRB 16896
#define ATT_SMEM 51712

__global__ void __launch_bounds__(256, 3) attn_kernel() {
    extern __shared__ __half smh[];
    float* Pf = reinterpret_cast<float*>(smh + 25344);
    const uint32_t sb = smem_u32(smh);
    const int tid = threadIdx.x;
    const int g0 = blockIdx.x * 4;

    for (int i = tid; i < 3072; i += 256) {
        int c16 = i & 255, tt = (i >> 8) & 3, arr = i >> 10;
        const __half* sp = (arr == 0) ? g_Qh : (arr == 1) ? g_Kh : g_Vh;
        int h = c16 >> 5, rr = c16 & 31;
        uint32_t dst = sb + (uint32_t)(arr * ARRB + tt * (ATPH * 2) + h * (AHPH * 2) + rr * 16);
        cpa16(dst, sp + (size_t)(g0 + tt) * DH + c16 * 8);
    }
    CP_COMMIT(); CP_WAIT(0);
    __syncthreads();

    const int t  = tid >> 6;
    const int hg = tid & 63;
    const int h  = hg >> 3, g = hg & 7;
    {
        const uint2* q4 = reinterpret_cast<const uint2*>(smh + t * ATPH + h * AHPH);
        const uint2* k4 = reinterpret_cast<const uint2*>(smh + 8448 + t * ATPH + g * AHPH);
        unsigned long long acc = 0ull;
        #pragma unroll 8
        for (int j = 0; j < 64; j++) {
            uint2 qw = q4[j], kw = k4[j];
            acc = fma2(h2_to_f2(qw.x), h2_to_f2(kw.x), acc);
            acc = fma2(h2_to_f2(qw.y), h2_to_f2(kw.y), acc);
        }
        float lo, hi; unpack2(acc, lo, hi);
        float L = (lo + hi) * 0.0625f;
        float m = L;
        m = fmaxf(m, __shfl_xor_sync(0xffffffffu, m, 1, 8));
        m = fmaxf(m, __shfl_xor_sync(0xffffffffu, m, 2, 8));
        m = fmaxf(m, __shfl_xor_sync(0xffffffffu, m, 4, 8));
        float e = __expf(L - m);
        float s = e;
        s += __shfl_xor_sync(0xffffffffu, s, 1, 8);
        s += __shfl_xor_sync(0xffffffffu, s, 2, 8);
        s += __shfl_xor_sync(0xffffffffu, s, 4, 8);
        Pf[t * 64 + h * 8 + g] = e / s;
    }
    __syncthreads();

    const int dx = tid & 63;
    const float* pbase = Pf + t * 64;
    #pragma unroll
    for (int dc = 0; dc < 8; dc++) {
        int c = dc * 64 + dx;
        int hh = c >> 6, dl = (c & 63) * 4;
        const float* pp = pbase + hh * 8;
        unsigned long long o01 = 0ull, o23 = 0ull;
        #pragma unroll
        for (int gg = 0; gg < 8; gg++) {
            float p = pp[gg];
            unsigned long long p2 = pack2(p, p);
            uint2 vw = *reinterpret_cast<const uint2*>(smh + 16896 + t * ATPH + gg * AHPH + dl);
            o01 = fma2(h2_to_f2(vw.x), p2, o01);
            o23 = fma2(h2_to_f2(vw.y), p2, o23);
        }
        float a0, a1, a2, a3;
        unpack2(o01, a0, a1); unpack2(o23, a2, a3);
        uint2 pk;
        __half2 h01 = __floats2half2_rn(a0, a1), h23 = __floats2half2_rn(a2, a3);
        pk.x = *reinterpret_cast<uint32_t*>(&h01);
        pk.y = *reinterpret_cast<uint32_t*>(&h23);
        *reinterpret_cast<uint2*>(g_Oh + (size_t)(g0 + t) * DH + c * 4) = pk;
    }
}

// ============================================================================
extern "C" void kernel_launch(void* const* d_in, const int* in_sizes, int n_in,
                              void* d_out, int out_size) {
    const float* x  = (const float*)d_in[0];
    const float* Wq = (const float*)d_in[1];
    const float* bq = (const float*)d_in[2];
    const float* Wk = (const float*)d_in[3];
    const float* bk = (const float*)d_in[4];
    const float* Wv = (const float*)d_in[5];
    const float* bv = (const float*)d_in[6];
    const float* Wo = (const float*)d_in[7];
    const float* bo = (const float*)d_in[8];
    float* out = (float*)d_out;

    cudaFuncSetAttribute(hgemm_ra, cudaFuncAttributeMaxDynamicSharedMemorySize, RA_SMEM);
    cudaFuncSetAttribute(hgemm_sk, cudaFuncAttributeMaxDynamicSharedMemorySize, GSMEM);
    cudaFuncSetAttribute(attn_kernel, cudaFuncAttributeMaxDynamicSharedMemorySize, ATT_SMEM);

    __half *Xh, *Qh, *Kh, *Vh, *Oh, *Wqd, *Wkd, *Wvd, *Wod;
    cudaGetSymbolAddress((void**)&Xh, g_Xh);
    cudaGetSymbolAddress((void**)&Qh, g_Qh);
    cudaGetSymbolAddress((void**)&Kh, g_Kh);
    cudaGetSymbolAddress((void**)&Vh, g_Vh);
    cudaGetSymbolAddress((void**)&Oh, g_Oh);
    cudaGetSymbolAddress((void**)&Wqd, g_Wq); cudaGetSymbolAddress((void**)&Wkd, g_Wk);
    cudaGetSymbolAddress((void**)&Wvd, g_Wv); cudaGetSymbolAddress((void**)&Wod, g_Wo);

    // prep
    xconv<<<4096, 256>>>((const float4*)x);
    wconv_all<<<dim3(128, 4), 256>>>(Wq, Wk, Wv, Wo);

    // QKV projections: A-resident GEMM, M=16384, N=2048, K=256
    dim3 g1(TOK / 128, DH / 128, 1);
    hgemm_ra<<<g1, 256, RA_SMEM>>>(Xh, DIN, Wqd, DIN, bq, Qh, DH);
    hgemm_ra<<<g1, 256, RA_SMEM>>>(Xh, DIN, Wkd, DIN, bk, Kh, DH);
    hgemm_ra<<<g1, 256, RA_SMEM>>>(Xh, DIN, Wvd, DIN, bv, Vh, DH);

    // attention v3
    attn_kernel<<<TOK / 4, 256, ATT_SMEM>>>();

    // out-proj: M=16384, N=256, K=2048 split-K x4, atomic accumulate onto bias
    biasfill<<<(TOK * DIN / 4) / 256, 256>>>(out, bo);
    dim3 g2(TOK / 128, DIN / 128, 4);
    hgemm_sk<<<g2, 256, GSMEM>>>(Oh, DH, Wod, DH, out, DIN, DH / 4);
}

// round 16
// speedup vs baseline: 1.4844x; 1.0110x over previous
#include <cuda_runtime.h>
#include <cuda_fp16.h>
#include <cstdint>

#define TOK   16384
#define DIN   256
#define DH    2048
#define NQKV  (3 * DH)
#define HEADS 8

// ---------------- device scratch ----------------
__device__ __half g_Xh[(size_t)TOK * DIN];
__device__ __half g_QKV[(size_t)TOK * NQKV];   // [t][Q|K|V]
__device__ __half g_Oh[(size_t)TOK * DH];
__device__ __half g_Wqkv[NQKV * DIN];          // [n][k], rows: Wq, Wk, Wv
__device__ __half g_Wo[DIN * DH];              // Wo^T [n=256][k=2048]
__device__ float  g_bqkv[NQKV];

// ---------------- helpers ----------------
__device__ __forceinline__ uint32_t smem_u32(const void* p) {
    uint32_t a;
    asm("{ .reg .u64 t; cvta.to.shared.u64 t, %1; cvt.u32.u64 %0, t; }" : "=r"(a) : "l"(p));
    return a;
}
__device__ __forceinline__ void cpa16(uint32_t dst, const void* src) {
    asm volatile("cp.async.cg.shared.global [%0], [%1], 16;" :: "r"(dst), "l"(src));
}
#define CP_COMMIT() asm volatile("cp.async.commit_group;" ::: "memory")
#define CP_WAIT(n)  asm volatile("cp.async.wait_group %0;" :: "n"(n) : "memory")

#define LDSM4(r, a) asm volatile( \
    "ldmatrix.sync.aligned.m8n8.x4.shared.b16 {%0,%1,%2,%3}, [%4];" \
    : "=r"((r)[0]), "=r"((r)[1]), "=r"((r)[2]), "=r"((r)[3]) : "r"(a))

#define MMA16816(c, a, b0, b1) asm volatile( \
    "mma.sync.aligned.m16n8k16.row.col.f32.f16.f16.f32 " \
    "{%0,%1,%2,%3}, {%4,%5,%6,%7}, {%8,%9}, {%0,%1,%2,%3};" \
    : "+f"((c)[0]), "+f"((c)[1]), "+f"((c)[2]), "+f"((c)[3]) \
    : "r"((a)[0]), "r"((a)[1]), "r"((a)[2]), "r"((a)[3]), "r"(b0), "r"(b1))

// packed fp32x2 FMA (B300 FFMA2)
__device__ __forceinline__ unsigned long long fma2(unsigned long long a,
                                                   unsigned long long b,
                                                   unsigned long long c) {
    unsigned long long d;
    asm("fma.rn.f32x2 %0, %1, %2, %3;" : "=l"(d) : "l"(a), "l"(b), "l"(c));
    return d;
}
__device__ __forceinline__ unsigned long long pack2(float x, float y) {
    unsigned long long r;
    asm("mov.b64 %0, {%1, %2};" : "=l"(r) : "f"(x), "f"(y));
    return r;
}
__device__ __forceinline__ void unpack2(unsigned long long v, float& x, float& y) {
    asm("mov.b64 {%0, %1}, %2;" : "=f"(x), "=f"(y) : "l"(v));
}
__device__ __forceinline__ unsigned long long h2_to_f2(uint32_t h2) {
    float2 f = __half22float2(*reinterpret_cast<const __half2*>(&h2));
    return pack2(f.x, f.y);
}

// ============================================================================
// X convert: fp32 -> fp16
// ============================================================================
__global__ void xconv(const float4* __restrict__ x) {
    size_t i = (size_t)blockIdx.x * blockDim.x + threadIdx.x;
    float4 f = x[i];
    __half2* p = reinterpret_cast<__half2*>(g_Xh) + 2 * i;
    p[0] = __floats2half2_rn(f.x, f.y);
    p[1] = __floats2half2_rn(f.z, f.w);
}

// ============================================================================
// weight transpose: W[K][N] -> [N][K] fp16, QKV concatenated; bias concat
// ============================================================================
__global__ void wconv_all(const float* __restrict__ Wq, const float* __restrict__ Wk,
                          const float* __restrict__ Wv, const float* __restrict__ Wo,
                          const float* __restrict__ bq, const float* __restrict__ bk,
                          const float* __restrict__ bv) {
    __shared__ float s[64][65];
    const int which = blockIdx.y;
    const float* W; __half* oh; int K, N;
    if (which == 0)      { W = Wq; oh = g_Wqkv;                K = DIN; N = DH; }
    else if (which == 1) { W = Wk; oh = g_Wqkv + DH * DIN;     K = DIN; N = DH; }
    else if (which == 2) { W = Wv; oh = g_Wqkv + 2 * DH * DIN; K = DIN; N = DH; }
    else                 { W = Wo; oh = g_Wo;                  K = DH;  N = DIN; }
    const int nt = N / 64;
    const int n0 = (blockIdx.x % nt) * 64, k0 = (blockIdx.x / nt) * 64;
    const int tx = threadIdx.x & 63, ty = threadIdx.x >> 6;
    for (int r = ty; r < 64; r += 4)
        s[r][tx] = W[(size_t)(k0 + r) * N + n0 + tx];
    __syncthreads();
    for (int r = ty; r < 64; r += 4)
        oh[(size_t)(n0 + r) * K + k0 + tx] = __float2half_rn(s[tx][r]);
    if (which < 3 && blockIdx.x == 0) {
        const float* b = (which == 0) ? bq : (which == 1) ? bk : bv;
        for (int i = threadIdx.x; i < DH; i += 256)
            g_bqkv[which * DH + i] = b[i];
    }
}

// ============================================================================
// bias prefill for split-K output: out[t][c] = bo[c]  (4096 blocks x 256)
// ============================================================================
__global__ void biasfill(float* __restrict__ out, const float* __restrict__ bo) {
    __shared__ float4 sb[64];
    if (threadIdx.x < 64) sb[threadIdx.x] = ((const float4*)bo)[threadIdx.x];
    __syncthreads();
    size_t i = (size_t)blockIdx.x * blockDim.x + threadIdx.x;
    ((float4*)out)[i] = sb[i & 63];
}

// ============================================================================
// hgemm_ra: A-RESIDENT fp16 TN GEMM for K=256, software-pipelined fragments.
// CTA 128x128, 8 warps (2m x 4n), warp tile 64x32.
// A tile resident (pitch 528B, 67584B); B streamed in k-iter PAIRS (double buf).
// Inner loop: all 4 B frags preloaded per kt; A frags double-buffered (1 mf ahead).
// smem = 67584 + 40960 = 108544B -> 2 CTA/SM.
// ============================================================================
#define RA_APITCH 528
#define RA_BOFF   67584
#define RA_SMEM   (67584 + 40960)

__global__ void __launch_bounds__(256, 2)
hgemm_ra(const __half* __restrict__ A, int lda,
         const __half* __restrict__ B, int ldb,
         const float* __restrict__ bias, __half* __restrict__ C, int ldc)
{
    extern __shared__ char smem[];
    const uint32_t sbase = smem_u32(smem);
    const int tid = threadIdx.x, lane = tid & 31, wid = tid >> 5;
    const int wm = wid >> 2, wn = wid & 3;
    const size_t m0 = (size_t)blockIdx.x * 128;
    const size_t n0 = (size_t)blockIdx.y * 128;

    float acc[4][4][4];
    #pragma unroll
    for (int a = 0; a < 4; a++)
        #pragma unroll
        for (int b = 0; b < 4; b++)
            #pragma unroll
            for (int c = 0; c < 4; c++) acc[a][b][c] = 0.f;

    // ---- load A resident: 4096 16B chunks, 16 per thread ----
    #pragma unroll
    for (int i = 0; i < 16; i++) {
        int c = tid + i * 256;
        int row = c >> 5, k16 = c & 31;
        cpa16(sbase + row * RA_APITCH + k16 * 16, A + (m0 + row) * (size_t)lda + k16 * 8);
    }

    #define RA_LOAD_PAIR(p, ss) do { \
        _Pragma("unroll") \
        for (int i = 0; i < 4; i++) { \
            int c = tid + i * 256; \
            int it = c >> 9, row = (c >> 2) & 127, ch = c & 3; \
            cpa16(sbase + RA_BOFF + (ss) * 20480 + it * 10240 + row * 80 + ch * 16, \
                  B + (n0 + row) * (size_t)ldb + (2 * (p) + it) * 32 + ch * 8); \
        } \
    } while (0)

    RA_LOAD_PAIR(0, 0);
    CP_COMMIT();
    CP_WAIT(0);
    __syncthreads();

    const uint32_t arow0 = sbase + (wm * 64 + (lane & 15)) * RA_APITCH + (lane >> 4) * 16;

    #pragma unroll
    for (int p = 0; p < 4; p++) {
        if (p + 1 < 4) { RA_LOAD_PAIR(p + 1, (p + 1) & 1); CP_COMMIT(); }

        #pragma unroll
        for (int it = 0; it < 2; it++) {
            const int kt = 2 * p + it;
            const uint32_t bs = sbase + RA_BOFF + (p & 1) * 20480 + it * 10240;
            const uint32_t brow = bs + (wn * 32 + (lane & 15)) * 80 + (lane >> 4) * 16;
            const uint32_t arow = arow0 + kt * 64;

            // preload all B fragments for this kt (both kh, both ng)
            uint32_t bf[2][2][4];
            LDSM4(bf[0][0], brow);
            LDSM4(bf[0][1], brow + 1280);
            LDSM4(bf[1][0], brow + 32);
            LDSM4(bf[1][1], brow + 1280 + 32);

            // A-fragment double buffer: ah[mf&1] holds fragment (kh, mf)
            uint32_t ah[2][4];
            LDSM4(ah[0], arow);
            #pragma unroll
            for (int kh = 0; kh < 2; kh++) {
                #pragma unroll
                for (int mf = 0; mf < 4; mf++) {
                    if (mf + 1 < 4)
                        LDSM4(ah[(mf + 1) & 1], arow + (mf + 1) * (16 * RA_APITCH) + kh * 32);
                    else if (kh == 0)
                        LDSM4(ah[0], arow + 32);
                    #pragma unroll
                    for (int ng = 0; ng < 2; ng++) {
                        #pragma unroll
                        for (int nn = 0; nn < 2; nn++)
                            MMA16816(acc[mf][ng * 2 + nn], ah[mf & 1],
                                     bf[kh][ng][nn], bf[kh][ng][nn + 2]);
                    }
                }
            }
        }
        if (p + 1 < 4) { CP_WAIT(0); __syncthreads(); }
    }

    // ---- epilogue: half out + bias ----
    #pragma unroll
    for (int mf = 0; mf < 4; mf++) {
        const size_t row = m0 + wm * 64 + mf * 16 + (lane >> 2);
        #pragma unroll
        for (int nf = 0; nf < 4; nf++) {
            const size_t col = n0 + wn * 32 + nf * 8 + (lane & 3) * 2;
            const float b0 = __ldg(bias + col), b1 = __ldg(bias + col + 1);
            *reinterpret_cast<__half2*>(C + row * (size_t)ldc + col) =
                __floats2half2_rn(acc[mf][nf][0] + b0, acc[mf][nf][1] + b1);
            *reinterpret_cast<__half2*>(C + (row + 8) * (size_t)ldc + col) =
                __floats2half2_rn(acc[mf][nf][2] + b0, acc[mf][nf][3] + b1);
        }
    }
}

// ============================================================================
// streaming fp16 TN GEMM: CTA 128x128, 8 warps, BK=32, 4-stage,
// float atomicAdd epilogue (bias prefilled) for split-K out-proj.
// ============================================================================
#define GST   20480
#define GSMEM (4 * GST)

__global__ void __launch_bounds__(256, 2)
hgemm_sk(const __half* __restrict__ A, int lda,
         const __half* __restrict__ B, int ldb,
         float* __restrict__ C, int ldc, int K)
{
    extern __shared__ char smem[];
    const uint32_t sbase = smem_u32(smem);
    const int tid = threadIdx.x, lane = tid & 31, wid = tid >> 5;
    const int wm = wid >> 2, wn = wid & 3;
    const size_t m0 = (size_t)blockIdx.x * 128;
    const size_t n0 = (size_t)blockIdx.y * 128;
    const size_t k0 = (size_t)blockIdx.z * K;

    float acc[4][4][4];
    #pragma unroll
    for (int a = 0; a < 4; a++)
        #pragma unroll
        for (int b = 0; b < 4; b++)
            #pragma unroll
            for (int c = 0; c < 4; c++) acc[a][b][c] = 0.f;

    const int r = tid >> 1;
    const int cc0 = (tid & 1) * 2;
    const int KT = K / 32;

    #define LOAD_STAGE(s, kb) do { \
        uint32_t d = sbase + (s) * GST; \
        const __half* pa = A + (m0 + r) * (size_t)lda + k0 + (kb); \
        const __half* pb = B + (n0 + r) * (size_t)ldb + k0 + (kb); \
        cpa16(d +         r * 80 + cc0 * 16,       pa + cc0 * 8); \
        cpa16(d +         r * 80 + (cc0 + 1) * 16, pa + (cc0 + 1) * 8); \
        cpa16(d + 10240 + r * 80 + cc0 * 16,       pb + cc0 * 8); \
        cpa16(d + 10240 + r * 80 + (cc0 + 1) * 16, pb + (cc0 + 1) * 8); \
    } while (0)

    LOAD_STAGE(0, 0); CP_COMMIT();
    if (KT > 1) { LOAD_STAGE(1, 32); CP_COMMIT(); }
    if (KT > 2) { LOAD_STAGE(2, 64); CP_COMMIT(); }

    for (int kt = 0; kt < KT; kt++) {
        if (kt + 1 >= KT)      CP_WAIT(0);
        else if (kt + 2 >= KT) CP_WAIT(1);
        else                   CP_WAIT(2);
        __syncthreads();
        if (kt + 3 < KT) { LOAD_STAGE((kt + 3) & 3, (kt + 3) * 32); CP_COMMIT(); }

        const uint32_t s = sbase + (kt & 3) * GST;
        const uint32_t arow = s +         (wm * 64 + (lane & 15)) * 80 + (lane >> 4) * 16;
        const uint32_t brow = s + 10240 + (wn * 32 + (lane & 15)) * 80 + (lane >> 4) * 16;

        #pragma unroll
        for (int kh = 0; kh < 2; kh++) {
            uint32_t bf[2][4];
            LDSM4(bf[0], brow + kh * 32);
            LDSM4(bf[1], brow + 1280 + kh * 32);
            #pragma unroll
            for (int mf = 0; mf < 4; mf++) {
                uint32_t ah[4];
                LDSM4(ah, arow + mf * 1280 + kh * 32);
                #pragma unroll
                for (int ng = 0; ng < 2; ng++) {
                    #pragma unroll
                    for (int nn = 0; nn < 2; nn++)
                        MMA16816(acc[mf][ng * 2 + nn], ah, bf[ng][nn], bf[ng][nn + 2]);
                }
            }
        }
    }

    #pragma unroll
    for (int mf = 0; mf < 4; mf++) {
        const size_t row = m0 + wm * 64 + mf * 16 + (lane >> 2);
        #pragma unroll
        for (int nf = 0; nf < 4; nf++) {
            const size_t col = n0 + wn * 32 + nf * 8 + (lane & 3) * 2;
            atomicAdd(C + row * (size_t)ldc + col,           acc[mf][nf][0]);
            atomicAdd(C + row * (size_t)ldc + col + 1,       acc[mf][nf][1]);
            atomicAdd(C + (row + 8) * (size_t)ldc + col,     acc[mf][nf][2]);
            atomicAdd(C + (row + 8) * (size_t)ldc + col + 1, acc[mf][nf][3]);
        }
    }
}

// ============================================================================
// attention v3 (R14-proven), reading combined QKV buffer [t][6144].
// ============================================================================
#define AHPH 264
#define ATPH 2112
#define ARRB 16896
#define ATT_SMEM 51712

__global__ void __launch_bounds__(256, 3) attn_kernel() {
    extern __shared__ __half smh[];
    float* Pf = reinterpret_cast<float*>(smh + 25344);
    const uint32_t sb = smem_u32(smh);
    const int tid = threadIdx.x;
    const int g0 = blockIdx.x * 4;

    for (int i = tid; i < 3072; i += 256) {
        int c16 = i & 255, tt = (i >> 8) & 3, arr = i >> 10;
        int h = c16 >> 5, rr = c16 & 31;
        uint32_t dst = sb + (uint32_t)(arr * ARRB + tt * (ATPH * 2) + h * (AHPH * 2) + rr * 16);
        cpa16(dst, g_QKV + (size_t)(g0 + tt) * NQKV + arr * DH + c16 * 8);
    }
    CP_COMMIT(); CP_WAIT(0);
    __syncthreads();

    const int t  = tid >> 6;
    const int hg = tid & 63;
    const int h  = hg >> 3, g = hg & 7;
    {
        const uint2* q4 = reinterpret_cast<const uint2*>(smh + t * ATPH + h * AHPH);
        const uint2* k4 = reinterpret_cast<const uint2*>(smh + 8448 + t * ATPH + g * AHPH);
        unsigned long long acc = 0ull;
        #pragma unroll 8
        for (int j = 0; j < 64; j++) {
            uint2 qw = q4[j], kw = k4[j];
            acc = fma2(h2_to_f2(qw.x), h2_to_f2(kw.x), acc);
            acc = fma2(h2_to_f2(qw.y), h2_to_f2(kw.y), acc);
        }
        float lo, hi; unpack2(acc, lo, hi);
        float L = (lo + hi) * 0.0625f;
        float m = L;
        m = fmaxf(m, __shfl_xor_sync(0xffffffffu, m, 1, 8));
        m = fmaxf(m, __shfl_xor_sync(0xffffffffu, m, 2, 8));
        m = fmaxf(m, __shfl_xor_sync(0xffffffffu, m, 4, 8));
        float e = __expf(L - m);
        float s = e;
        s += __shfl_xor_sync(0xffffffffu, s, 1, 8);
        s += __shfl_xor_sync(0xffffffffu, s, 2, 8);
        s += __shfl_xor_sync(0xffffffffu, s, 4, 8);
        Pf[t * 64 + h * 8 + g] = e / s;
    }
    __syncthreads();

    const int dx = tid & 63;
    const float* pbase = Pf + t * 64;
    #pragma unroll
    for (int dc = 0; dc < 8; dc++) {
        int c = dc * 64 + dx;
        int hh = c >> 6, dl = (c & 63) * 4;
        const float* pp = pbase + hh * 8;
        unsigned long long o01 = 0ull, o23 = 0ull;
        #pragma unroll
        for (int gg = 0; gg < 8; gg++) {
            float p = pp[gg];
            unsigned long long p2 = pack2(p, p);
            uint2 vw = *reinterpret_cast<const uint2*>(smh + 16896 + t * ATPH + gg * AHPH + dl);
            o01 = fma2(h2_to_f2(vw.x), p2, o01);
            o23 = fma2(h2_to_f2(vw.y), p2, o23);
        }
        float a0, a1, a2, a3;
        unpack2(o01, a0, a1); unpack2(o23, a2, a3);
        uint2 pk;
        __half2 h01 = __floats2half2_rn(a0, a1), h23 = __floats2half2_rn(a2, a3);
        pk.x = *reinterpret_cast<uint32_t*>(&h01);
        pk.y = *reinterpret_cast<uint32_t*>(&h23);
        *reinterpret_cast<uint2*>(g_Oh + (size_t)(g0 + t) * DH + c * 4) = pk;
    }
}

// ============================================================================
extern "C" void kernel_launch(void* const* d_in, const int* in_sizes, int n_in,
                              void* d_out, int out_size) {
    const float* x  = (const float*)d_in[0];
    const float* Wq = (const float*)d_in[1];
    const float* bq = (const float*)d_in[2];
    const float* Wk = (const float*)d_in[3];
    const float* bk = (const float*)d_in[4];
    const float* Wv = (const float*)d_in[5];
    const float* bv = (const float*)d_in[6];
    const float* Wo = (const float*)d_in[7];
    const float* bo = (const float*)d_in[8];
    float* out = (float*)d_out;

    cudaFuncSetAttribute(hgemm_ra, cudaFuncAttributeMaxDynamicSharedMemorySize, RA_SMEM);
    cudaFuncSetAttribute(hgemm_sk, cudaFuncAttributeMaxDynamicSharedMemorySize, GSMEM);
    cudaFuncSetAttribute(attn_kernel, cudaFuncAttributeMaxDynamicSharedMemorySize, ATT_SMEM);

    __half *Xh, *QKV, *Oh, *Wqkv, *Wod;
    float *bqkv;
    cudaGetSymbolAddress((void**)&Xh, g_Xh);
    cudaGetSymbolAddress((void**)&QKV, g_QKV);
    cudaGetSymbolAddress((void**)&Oh, g_Oh);
    cudaGetSymbolAddress((void**)&Wqkv, g_Wqkv);
    cudaGetSymbolAddress((void**)&Wod, g_Wo);
    cudaGetSymbolAddress((void**)&bqkv, g_bqkv);

    // prep
    xconv<<<4096, 256>>>((const float4*)x);
    wconv_all<<<dim3(128, 4), 256>>>(Wq, Wk, Wv, Wo, bq, bk, bv);

    // fused QKV projection: M=16384, N=6144, K=256 (A-resident, pipelined)
    dim3 g1(TOK / 128, NQKV / 128, 1);
    hgemm_ra<<<g1, 256, RA_SMEM>>>(Xh, DIN, Wqkv, DIN, bqkv, QKV, NQKV);

    // attention v3
    attn_kernel<<<TOK / 4, 256, ATT_SMEM>>>();

    // out-proj: M=16384, N=256, K=2048 split-K x4, atomic accumulate onto bias
    biasfill<<<(TOK * DIN / 4) / 256, 256>>>(out, bo);
    dim3 g2(TOK / 128, DIN / 128, 4);
    hgemm_sk<<<g2, 256, GSMEM>>>(Oh, DH, Wod, DH, out, DIN, DH / 4);
}